// round 9
// baseline (speedup 1.0000x reference)
#include <cuda_runtime.h>
#include <math.h>

#define B_ 64
#define L_ 512
#define D_ 768
#define S_ 8

// ---------------- device scratch (allocation-free) ----------------
__device__ float g_sent[B_ * 4 * D_];   // rows per batch: s5,s6,s7, zero-pad
__device__ float g_acc[320 * D_];       // accA1(64) | accC1(128) | accG2(64) | accC2(64)

// packed f32x2 FMA (sm_103a: only reachable via PTX)
#define FMA2(acc, a, b) \
    asm("fma.rn.f32x2 %0, %1, %2, %0;" : "+l"(acc) : "l"(a), "l"(b))

// ---------------- K1: segment means (rows 5,6,7), 2 D-halves per row + zeroing ----------------
__global__ void __launch_bounds__(96) k_sent(const float* __restrict__ bert,
                                             const int* __restrict__ seg) {
    int bid = blockIdx.x;
    int t = threadIdx.x;
    if (bid >= 384) {
        int zt = (bid - 384) * 96 + t;
        const int stride = 160 * 96;
        for (int i = zt; i < 320 * D_; i += stride) g_acc[i] = 0.f;
        return;
    }
    int half = bid & 1;
    int r = (bid >> 1) % 3;
    int b = bid / 6;
    int s = 5 + r;
    int start = seg[b * 9 + s];
    int end   = seg[b * 9 + s + 1];
    int col = half * 96 + t;               // float4 column 0..191
    const float4* base = (const float4*)(bert + (size_t)b * L_ * D_);
    float4 a[8];
#pragma unroll
    for (int i = 0; i < 8; i++) a[i] = make_float4(0.f, 0.f, 0.f, 0.f);
    int l = start;
    for (; l + 8 <= end; l += 8) {
#pragma unroll
        for (int i = 0; i < 8; i++) {
            float4 v = base[(l + i) * 192 + col];
            a[i].x += v.x; a[i].y += v.y; a[i].z += v.z; a[i].w += v.w;
        }
    }
    for (; l < end; ++l) {
        float4 v = base[l * 192 + col];
        a[0].x += v.x; a[0].y += v.y; a[0].z += v.z; a[0].w += v.w;
    }
#pragma unroll
    for (int i = 1; i < 8; i++) {
        a[0].x += a[i].x; a[0].y += a[i].y; a[0].z += a[i].z; a[0].w += a[i].w;
    }
    float inv = 1.f / (float)(end - start);
    float4 outv = make_float4(a[0].x * inv, a[0].y * inv, a[0].z * inv, a[0].w * inv);
    ((float4*)g_sent)[b * 768 + r * 192 + col] = outv;
    if (r == 2)
        ((float4*)g_sent)[b * 768 + 3 * 192 + col] = make_float4(0.f, 0.f, 0.f, 0.f);
}

// ---------------- split-K GEMM, register-prefetch pipelined, packed f32x2 FMA ----------------
// MODE 0: A = g_sent row7                      W = gc1_w  [K,768]   C = accA1
// MODE 1: A = conv1 im2col(g_sent)             W = conv1_w [768,K]  C = accC1
// MODE 2: A = tanh(accA1+gc1_b)                W = gc2_w  [K,768]   C = accG2
// MODE 3: A = im2col(tanh(accC1+conv1_b))      W = conv2_w [768,K]  C = accC2
// kslice = 96 (NKB = 3).
template <int MODE>
__device__ __forceinline__ void gemm_body(
    const float* __restrict__ W, float* __restrict__ C,
    const float* __restrict__ bias,
    int K, int nNt, int nMt, int bid,
    float2 (*As2)[32], float (*Bs)[68])
{
    constexpr bool BT = (MODE == 1 || MODE == 3);
    const float* accA1 = g_acc;
    const float* accC1 = g_acc + 64 * 768;

    int nt = bid % nNt;
    int mt = (bid / nNt) % nMt;
    int ks = bid / (nNt * nMt);
    int k0 = ks * 96;
    const int NKB = 3;

    int tid = threadIdx.x;
    int tx = tid & 15, ty = tid >> 4;
    int n0 = nt * 64;
    int mbase = mt * 64;
    int ka = tid & 31, m0 = tid >> 5;

    float rA[8], rB[8];

    auto loadA = [&](int kb) {
        int kg = kb + ka;
        int e = 0, tap = 0;
        float bk = 0.f;
        if (MODE == 1 || MODE == 3) { e = kg / 3; tap = kg - e * 3; }
        if (MODE == 2) bk = bias[kg];
        if (MODE == 3) bk = bias[e];
#pragma unroll
        for (int j = 0; j < 8; j++) {
            int m = mbase + m0 + j * 8;
            if (MODE == 0)
                rA[j] = g_sent[m * 3072 + 1536 + kg];
            else if (MODE == 1)
                rA[j] = g_sent[(m >> 1) * 3072 + ((m & 1) + tap) * 768 + e];
            else if (MODE == 2)
                rA[j] = tanhf(accA1[m * 768 + kg] + bk);
            else
                rA[j] = (tap == 2) ? 0.f
                        : tanhf(accC1[(m * 2 + tap) * 768 + e] + bk);
        }
    };
    auto loadB = [&](int kb) {
        if (!BT) {          // W[K,768]: rows kb+ty, kb+ty+16; float4 along n
#pragma unroll
            for (int j = 0; j < 2; j++) {
                float4 v = *(const float4*)&W[(size_t)(kb + ty + j * 16) * 768 + n0 + tx * 4];
                rB[j * 4 + 0] = v.x; rB[j * 4 + 1] = v.y;
                rB[j * 4 + 2] = v.z; rB[j * 4 + 3] = v.w;
            }
        } else {            // W[768,K]: coalesced along k
#pragma unroll
            for (int j = 0; j < 8; j++)
                rB[j] = W[(size_t)(n0 + m0 + j * 8) * K + kb + ka];
        }
    };
    auto store = [&]() {
#pragma unroll
        for (int j = 0; j < 8; j++)
            As2[m0 + j * 8][ka] = make_float2(rA[j], rA[j]);
        if (!BT) {
#pragma unroll
            for (int j = 0; j < 2; j++)
                *(float4*)&Bs[ty + j * 16][tx * 4] =
                    make_float4(rB[j * 4], rB[j * 4 + 1], rB[j * 4 + 2], rB[j * 4 + 3]);
        } else {
#pragma unroll
            for (int j = 0; j < 8; j++)
                Bs[ka][m0 + j * 8] = rB[j];
        }
    };

    unsigned long long acc[4][2] = {};

    loadA(k0); loadB(k0);
    for (int i = 0; i < NKB; i++) {
        store();
        __syncthreads();
        if (i + 1 < NKB) {               // prefetch next tile: overlaps the FMA loop
            loadA(k0 + (i + 1) * 32);
            loadB(k0 + (i + 1) * 32);
        }
#pragma unroll
        for (int kk = 0; kk < 32; kk++) {
            unsigned long long a0 = *(const unsigned long long*)&As2[ty * 4 + 0][kk];
            unsigned long long a1 = *(const unsigned long long*)&As2[ty * 4 + 1][kk];
            unsigned long long a2 = *(const unsigned long long*)&As2[ty * 4 + 2][kk];
            unsigned long long a3 = *(const unsigned long long*)&As2[ty * 4 + 3][kk];
            ulonglong2 bb = *(const ulonglong2*)&Bs[kk][tx * 4];
            FMA2(acc[0][0], a0, bb.x); FMA2(acc[0][1], a0, bb.y);
            FMA2(acc[1][0], a1, bb.x); FMA2(acc[1][1], a1, bb.y);
            FMA2(acc[2][0], a2, bb.x); FMA2(acc[2][1], a2, bb.y);
            FMA2(acc[3][0], a3, bb.x); FMA2(acc[3][1], a3, bb.y);
        }
        __syncthreads();
    }
    float* Cb = C + (size_t)mbase * 768 + n0;
#pragma unroll
    for (int i = 0; i < 4; i++) {
        float2 p0 = *(float2*)&acc[i][0];
        float2 p1 = *(float2*)&acc[i][1];
        float* row = &Cb[(ty * 4 + i) * 768 + tx * 4];
        atomicAdd(&row[0], p0.x);
        atomicAdd(&row[1], p0.y);
        atomicAdd(&row[2], p1.x);
        atomicAdd(&row[3], p1.y);
    }
}

// stage 1: gemm1 (96 blocks) + conv1 (576 blocks), kslice=96
__global__ void __launch_bounds__(256, 2) k_stage1(const float* __restrict__ gc1_w,
                                                   const float* __restrict__ conv1_w) {
    __shared__ __align__(16) float2 As2[64][32];
    __shared__ __align__(16) float  Bs[32][68];
    if ((int)blockIdx.x < 96)
        gemm_body<0>(gc1_w, g_acc, nullptr, 768, 12, 1, blockIdx.x, As2, Bs);
    else
        gemm_body<1>(conv1_w, g_acc + 64 * 768, nullptr, 2304, 12, 2, blockIdx.x - 96, As2, Bs);
}

// stage 2: gemm2 (96) + conv2 (288), fused tanh-epilogue A, kslice=96
__global__ void __launch_bounds__(256, 2) k_stage2(const float* __restrict__ gc2_w,
                                                   const float* __restrict__ conv2_w,
                                                   const float* __restrict__ gc1_b,
                                                   const float* __restrict__ conv1_b) {
    __shared__ __align__(16) float2 As2[64][32];
    __shared__ __align__(16) float  Bs[32][68];
    if ((int)blockIdx.x < 96)
        gemm_body<2>(gc2_w, g_acc + 192 * 768, gc1_b, 768, 12, 1, blockIdx.x, As2, Bs);
    else
        gemm_body<3>(conv2_w, g_acc + 256 * 768, conv1_b, 2304, 12, 1, blockIdx.x - 96, As2, Bs);
}

// ---------------- warp all-reduce helpers ----------------
__device__ __forceinline__ float warpAllSum(float v) {
#pragma unroll
    for (int o = 16; o; o >>= 1) v += __shfl_xor_sync(0xffffffffu, v, o);
    return v;
}
__device__ __forceinline__ void warpAllSum2(float& a, float& b) {
#pragma unroll
    for (int o = 16; o; o >>= 1) {
        a += __shfl_xor_sync(0xffffffffu, a, o);
        b += __shfl_xor_sync(0xffffffffu, b, o);
    }
}
__device__ __forceinline__ void warpAllSum3(float& a, float& b, float& c) {
#pragma unroll
    for (int o = 16; o; o >>= 1) {
        a += __shfl_xor_sync(0xffffffffu, a, o);
        b += __shfl_xor_sync(0xffffffffu, b, o);
        c += __shfl_xor_sync(0xffffffffu, c, o);
    }
}

// ---------------- K4: hops + softmax + fc2. grid=64, block=96 (warp per branch) ----------------
__global__ void __launch_bounds__(96) k_final(
    const float* __restrict__ target, const float* __restrict__ gc2_b,
    const float* __restrict__ conv2_b, const float* __restrict__ ln_g,
    const float* __restrict__ ln_b, const float* __restrict__ fc2_w,
    const float* __restrict__ fc2_b, float* __restrict__ out)
{
    int b = blockIdx.x;
    int w = threadIdx.x >> 5;        // branch id: 0=g2, 1=conv, 2=tmask
    int lane = threadIdx.x & 31;
    const float* accG2 = g_acc + 192 * 768;
    const float* accC2 = g_acc + 256 * 768;

    __shared__ float ak[3][768];
    __shared__ float tks[3];

    float s7[24], v[24];
#pragma unroll
    for (int i = 0; i < 24; i++)
        s7[i] = g_sent[b * 3072 + 1536 + lane + i * 32];

    if (w == 2) {
        float ss = 0.f;
#pragma unroll
        for (int i = 0; i < 24; i++) ss += s7[i] * s7[i];
        ss = warpAllSum(ss);
#pragma unroll
        for (int i = 0; i < 24; i++)
            v[i] = __fdividef(1.f, 1.f + __expf(-ss * s7[i]));
    } else {
        const float* acc  = (w == 0) ? accG2 : accC2;
        const float* bias = (w == 0) ? gc2_b : conv2_b;
#pragma unroll
        for (int i = 0; i < 24; i++) {
            int d = lane + i * 32;
            v[i] = tanhf(acc[b * 768 + d] + bias[d]);
        }
    }

#pragma unroll
    for (int it = 0; it < 2; it++) {
        float pc = 0.f;
#pragma unroll
        for (int i = 0; i < 24; i++) pc += v[i] * s7[i];
        float c = warpAllSum(pc);
        float x[24], su = 0.f, sq = 0.f;
#pragma unroll
        for (int i = 0; i < 24; i++) {
            float xv = __fdividef(1.f, 1.f + __expf(-c * s7[i]));
            x[i] = xv; su += xv; sq += xv * xv;
        }
        warpAllSum2(su, sq);
        float mean = su * (1.f / 768.f);
        float m2   = sq * (1.f / 768.f);
        float rstd = rsqrtf(m2 - mean * mean + 1e-5f);
#pragma unroll
        for (int i = 0; i < 24; i++) {
            int d = lane + i * 32;
            v[i] = 0.5f * ((x[i] - mean) * rstd * ln_g[d] + ln_b[d]) + s7[i];
        }
    }

    float pt = 0.f;
#pragma unroll
    for (int i = 0; i < 24; i++) {
        int d = lane + i * 32;
        ak[w][d] = v[i];
        pt += v[i] * target[d];
    }
    pt = warpAllSum(pt);
    if (lane == 0) tks[w] = pt;
    __syncthreads();

    if (w == 0) {
        float t0 = tks[0], t1 = tks[1], t2 = tks[2];
        float mx = fmaxf(t0, fmaxf(t1, t2));
        float e0 = __expf(t0 - mx), e1 = __expf(t1 - mx), e2 = __expf(t2 - mx);
        float inv = __fdividef(1.f, e0 + e1 + e2);
        float w0 = e0 * inv, w1 = e1 * inv, w2 = e2 * inv;

        float pj0 = 0.f, pj1 = 0.f, pj2 = 0.f;
#pragma unroll
        for (int i = 0; i < 24; i++) {
            int d = lane + i * 32;
            float f0 = w0 * ak[0][d];
            float f1 = w1 * ak[1][d];
            float f2 = w2 * ak[2][d];
            const float* w_0 = &fc2_w[d * 3];
            const float* w_1 = &fc2_w[(768 + d) * 3];
            const float* w_2 = &fc2_w[(1536 + d) * 3];
            pj0 += f0 * w_0[0] + f1 * w_1[0] + f2 * w_2[0];
            pj1 += f0 * w_0[1] + f1 * w_1[1] + f2 * w_2[1];
            pj2 += f0 * w_0[2] + f1 * w_1[2] + f2 * w_2[2];
        }
        warpAllSum3(pj0, pj1, pj2);
        if (lane == 0) {
            out[b * 3 + 0] = pj0 + fc2_b[0];
            out[b * 3 + 1] = pj1 + fc2_b[1];
            out[b * 3 + 2] = pj2 + fc2_b[2];
        }
    }
}

// ---------------- launch ----------------
extern "C" void kernel_launch(void* const* d_in, const int* in_sizes, int n_in,
                              void* d_out, int out_size) {
    (void)in_sizes; (void)n_in; (void)out_size;
    const float* bert    = (const float*)d_in[0];
    const float* target  = (const float*)d_in[1];
    const float* gc1_w   = (const float*)d_in[2];
    const float* gc1_b   = (const float*)d_in[3];
    const float* gc2_w   = (const float*)d_in[4];
    const float* gc2_b   = (const float*)d_in[5];
    const float* conv1_w = (const float*)d_in[6];
    const float* conv1_b = (const float*)d_in[7];
    const float* conv2_w = (const float*)d_in[8];
    const float* conv2_b = (const float*)d_in[9];
    const float* ln_g    = (const float*)d_in[10];
    const float* ln_b    = (const float*)d_in[11];
    const float* fc2_w   = (const float*)d_in[12];
    const float* fc2_b   = (const float*)d_in[13];
    const int*   seg     = (const int*)d_in[14];
    float* out = (float*)d_out;

    k_sent<<<544, 96>>>(bert, seg);                           // means (384) + zeroing (160)
    k_stage1<<<672, 256>>>(gc1_w, conv1_w);                   // gemm1 + conv1
    k_stage2<<<384, 256>>>(gc2_w, conv2_w, gc1_b, conv1_b);   // gemm2 + conv2
    k_final<<<64, 96>>>(target, gc2_b, conv2_b, ln_g, ln_b, fc2_w, fc2_b, out);
}

// round 10
// speedup vs baseline: 1.0108x; 1.0108x over previous
#include <cuda_runtime.h>
#include <math.h>

#define B_ 64
#define L_ 512
#define D_ 768
#define S_ 8

// ---------------- device scratch (allocation-free) ----------------
__device__ float g_sent[B_ * 4 * D_];   // rows per batch: s5,s6,s7, zero-pad
__device__ float g_acc[320 * D_];       // accA1(64) | accC1(128) | accG2(64) | accC2(64)

// packed f32x2 FMA (sm_103a: only reachable via PTX)
#define FMA2(acc, a, b) \
    asm("fma.rn.f32x2 %0, %1, %2, %0;" : "+l"(acc) : "l"(a), "l"(b))

// ---------------- K1: segment means (rows 5,6,7), 2 D-halves per row + zeroing ----------------
__global__ void __launch_bounds__(96) k_sent(const float* __restrict__ bert,
                                             const int* __restrict__ seg) {
    int bid = blockIdx.x;
    int t = threadIdx.x;
    if (bid >= 384) {
        int zt = (bid - 384) * 96 + t;
        const int stride = 160 * 96;
        for (int i = zt; i < 320 * D_; i += stride) g_acc[i] = 0.f;
        return;
    }
    int half = bid & 1;
    int r = (bid >> 1) % 3;
    int b = bid / 6;
    int s = 5 + r;
    int start = seg[b * 9 + s];
    int end   = seg[b * 9 + s + 1];
    int col = half * 96 + t;               // float4 column 0..191
    const float4* base = (const float4*)(bert + (size_t)b * L_ * D_);
    float4 a[8];
#pragma unroll
    for (int i = 0; i < 8; i++) a[i] = make_float4(0.f, 0.f, 0.f, 0.f);
    int l = start;
    for (; l + 8 <= end; l += 8) {
#pragma unroll
        for (int i = 0; i < 8; i++) {
            float4 v = base[(l + i) * 192 + col];
            a[i].x += v.x; a[i].y += v.y; a[i].z += v.z; a[i].w += v.w;
        }
    }
    for (; l < end; ++l) {
        float4 v = base[l * 192 + col];
        a[0].x += v.x; a[0].y += v.y; a[0].z += v.z; a[0].w += v.w;
    }
#pragma unroll
    for (int i = 1; i < 8; i++) {
        a[0].x += a[i].x; a[0].y += a[i].y; a[0].z += a[i].z; a[0].w += a[i].w;
    }
    float inv = 1.f / (float)(end - start);
    float4 outv = make_float4(a[0].x * inv, a[0].y * inv, a[0].z * inv, a[0].w * inv);
    ((float4*)g_sent)[b * 768 + r * 192 + col] = outv;
    if (r == 2)
        ((float4*)g_sent)[b * 768 + 3 * 192 + col] = make_float4(0.f, 0.f, 0.f, 0.f);
}

// ---------------- split-K GEMM, register-prefetch pipelined, packed f32x2 FMA ----------------
// MODE 0: A = g_sent row7                      W = gc1_w  [K,768]   C = accA1
// MODE 1: A = conv1 im2col(g_sent)             W = conv1_w [768,K]  C = accC1
// MODE 2: A = tanh(accA1+gc1_b)                W = gc2_w  [K,768]   C = accG2
// MODE 3: A = im2col(tanh(accC1+conv1_b))      W = conv2_w [768,K]  C = accC2
// kslice = 96 (NKB = 3).
template <int MODE>
__device__ __forceinline__ void gemm_body(
    const float* __restrict__ W, float* __restrict__ C,
    const float* __restrict__ bias,
    int K, int nNt, int nMt, int bid,
    float2 (*As2)[32], float (*Bs)[68])
{
    constexpr bool BT = (MODE == 1 || MODE == 3);
    const float* accA1 = g_acc;
    const float* accC1 = g_acc + 64 * 768;

    int nt = bid % nNt;
    int mt = (bid / nNt) % nMt;
    int ks = bid / (nNt * nMt);
    int k0 = ks * 96;
    const int NKB = 3;

    int tid = threadIdx.x;
    int tx = tid & 15, ty = tid >> 4;
    int n0 = nt * 64;
    int mbase = mt * 64;
    int ka = tid & 31, m0 = tid >> 5;

    float rA[8], rB[8];

    auto loadA = [&](int kb) {
        int kg = kb + ka;
        int e = 0, tap = 0;
        float bk = 0.f;
        if (MODE == 1 || MODE == 3) { e = kg / 3; tap = kg - e * 3; }
        if (MODE == 2) bk = bias[kg];
        if (MODE == 3) bk = bias[e];
#pragma unroll
        for (int j = 0; j < 8; j++) {
            int m = mbase + m0 + j * 8;
            if (MODE == 0)
                rA[j] = g_sent[m * 3072 + 1536 + kg];
            else if (MODE == 1)
                rA[j] = g_sent[(m >> 1) * 3072 + ((m & 1) + tap) * 768 + e];
            else if (MODE == 2)
                rA[j] = tanhf(accA1[m * 768 + kg] + bk);
            else
                rA[j] = (tap == 2) ? 0.f
                        : tanhf(accC1[(m * 2 + tap) * 768 + e] + bk);
        }
    };
    auto loadB = [&](int kb) {
        if (!BT) {          // W[K,768]: rows kb+ty, kb+ty+16; float4 along n
#pragma unroll
            for (int j = 0; j < 2; j++) {
                float4 v = *(const float4*)&W[(size_t)(kb + ty + j * 16) * 768 + n0 + tx * 4];
                rB[j * 4 + 0] = v.x; rB[j * 4 + 1] = v.y;
                rB[j * 4 + 2] = v.z; rB[j * 4 + 3] = v.w;
            }
        } else {            // W[768,K]: coalesced along k
#pragma unroll
            for (int j = 0; j < 8; j++)
                rB[j] = W[(size_t)(n0 + m0 + j * 8) * K + kb + ka];
        }
    };
    auto store = [&]() {
#pragma unroll
        for (int j = 0; j < 8; j++)
            As2[m0 + j * 8][ka] = make_float2(rA[j], rA[j]);
        if (!BT) {
#pragma unroll
            for (int j = 0; j < 2; j++)
                *(float4*)&Bs[ty + j * 16][tx * 4] =
                    make_float4(rB[j * 4], rB[j * 4 + 1], rB[j * 4 + 2], rB[j * 4 + 3]);
        } else {
#pragma unroll
            for (int j = 0; j < 8; j++)
                Bs[ka][m0 + j * 8] = rB[j];
        }
    };

    unsigned long long acc[4][2] = {};

    loadA(k0); loadB(k0);
    for (int i = 0; i < NKB; i++) {
        store();
        __syncthreads();
        if (i + 1 < NKB) {               // prefetch next tile: overlaps the FMA loop
            loadA(k0 + (i + 1) * 32);
            loadB(k0 + (i + 1) * 32);
        }
#pragma unroll
        for (int kk = 0; kk < 32; kk++) {
            unsigned long long a0 = *(const unsigned long long*)&As2[ty * 4 + 0][kk];
            unsigned long long a1 = *(const unsigned long long*)&As2[ty * 4 + 1][kk];
            unsigned long long a2 = *(const unsigned long long*)&As2[ty * 4 + 2][kk];
            unsigned long long a3 = *(const unsigned long long*)&As2[ty * 4 + 3][kk];
            ulonglong2 bb = *(const ulonglong2*)&Bs[kk][tx * 4];
            FMA2(acc[0][0], a0, bb.x); FMA2(acc[0][1], a0, bb.y);
            FMA2(acc[1][0], a1, bb.x); FMA2(acc[1][1], a1, bb.y);
            FMA2(acc[2][0], a2, bb.x); FMA2(acc[2][1], a2, bb.y);
            FMA2(acc[3][0], a3, bb.x); FMA2(acc[3][1], a3, bb.y);
        }
        __syncthreads();
    }
    float* Cb = C + (size_t)mbase * 768 + n0;
#pragma unroll
    for (int i = 0; i < 4; i++) {
        float2 p0 = *(float2*)&acc[i][0];
        float2 p1 = *(float2*)&acc[i][1];
        float* row = &Cb[(ty * 4 + i) * 768 + tx * 4];
        atomicAdd(&row[0], p0.x);
        atomicAdd(&row[1], p0.y);
        atomicAdd(&row[2], p1.x);
        atomicAdd(&row[3], p1.y);
    }
}

// stage 1: gemm1 (96 blocks) + conv1 (576 blocks), kslice=96
__global__ void __launch_bounds__(256, 2) k_stage1(const float* __restrict__ gc1_w,
                                                   const float* __restrict__ conv1_w) {
    __shared__ __align__(16) float2 As2[64][32];
    __shared__ __align__(16) float  Bs[32][68];
    if ((int)blockIdx.x < 96)
        gemm_body<0>(gc1_w, g_acc, nullptr, 768, 12, 1, blockIdx.x, As2, Bs);
    else
        gemm_body<1>(conv1_w, g_acc + 64 * 768, nullptr, 2304, 12, 2, blockIdx.x - 96, As2, Bs);
}

// stage 2: gemm2 (96) + conv2 (288), fused tanh-epilogue A, kslice=96
__global__ void __launch_bounds__(256, 2) k_stage2(const float* __restrict__ gc2_w,
                                                   const float* __restrict__ conv2_w,
                                                   const float* __restrict__ gc1_b,
                                                   const float* __restrict__ conv1_b) {
    __shared__ __align__(16) float2 As2[64][32];
    __shared__ __align__(16) float  Bs[32][68];
    if ((int)blockIdx.x < 96)
        gemm_body<2>(gc2_w, g_acc + 192 * 768, gc1_b, 768, 12, 1, blockIdx.x, As2, Bs);
    else
        gemm_body<3>(conv2_w, g_acc + 256 * 768, conv1_b, 2304, 12, 1, blockIdx.x - 96, As2, Bs);
}

// ---------------- warp all-reduce helpers ----------------
__device__ __forceinline__ float warpAllSum(float v) {
#pragma unroll
    for (int o = 16; o; o >>= 1) v += __shfl_xor_sync(0xffffffffu, v, o);
    return v;
}
__device__ __forceinline__ void warpAllSum2(float& a, float& b) {
#pragma unroll
    for (int o = 16; o; o >>= 1) {
        a += __shfl_xor_sync(0xffffffffu, a, o);
        b += __shfl_xor_sync(0xffffffffu, b, o);
    }
}
__device__ __forceinline__ void warpAllSum3(float& a, float& b, float& c) {
#pragma unroll
    for (int o = 16; o; o >>= 1) {
        a += __shfl_xor_sync(0xffffffffu, a, o);
        b += __shfl_xor_sync(0xffffffffu, b, o);
        c += __shfl_xor_sync(0xffffffffu, c, o);
    }
}

// ---------------- K4: hops + softmax + fc2. grid=64, block=96 (warp per branch) ----------------
__global__ void __launch_bounds__(96) k_final(
    const float* __restrict__ target, const float* __restrict__ gc2_b,
    const float* __restrict__ conv2_b, const float* __restrict__ ln_g,
    const float* __restrict__ ln_b, const float* __restrict__ fc2_w,
    const float* __restrict__ fc2_b, float* __restrict__ out)
{
    int b = blockIdx.x;
    int w = threadIdx.x >> 5;        // branch id: 0=g2, 1=conv, 2=tmask
    int lane = threadIdx.x & 31;
    const float* accG2 = g_acc + 192 * 768;
    const float* accC2 = g_acc + 256 * 768;

    __shared__ float ak[3][768];
    __shared__ float tks[3];

    float s7[24], v[24];
#pragma unroll
    for (int i = 0; i < 24; i++)
        s7[i] = g_sent[b * 3072 + 1536 + lane + i * 32];

    if (w == 2) {
        float ss = 0.f;
#pragma unroll
        for (int i = 0; i < 24; i++) ss += s7[i] * s7[i];
        ss = warpAllSum(ss);
#pragma unroll
        for (int i = 0; i < 24; i++)
            v[i] = __fdividef(1.f, 1.f + __expf(-ss * s7[i]));
    } else {
        const float* acc  = (w == 0) ? accG2 : accC2;
        const float* bias = (w == 0) ? gc2_b : conv2_b;
#pragma unroll
        for (int i = 0; i < 24; i++) {
            int d = lane + i * 32;
            v[i] = tanhf(acc[b * 768 + d] + bias[d]);
        }
    }

#pragma unroll
    for (int it = 0; it < 2; it++) {
        float pc = 0.f;
#pragma unroll
        for (int i = 0; i < 24; i++) pc += v[i] * s7[i];
        float c = warpAllSum(pc);
        float x[24], su = 0.f, sq = 0.f;
#pragma unroll
        for (int i = 0; i < 24; i++) {
            float xv = __fdividef(1.f, 1.f + __expf(-c * s7[i]));
            x[i] = xv; su += xv; sq += xv * xv;
        }
        warpAllSum2(su, sq);
        float mean = su * (1.f / 768.f);
        float m2   = sq * (1.f / 768.f);
        float rstd = rsqrtf(m2 - mean * mean + 1e-5f);
#pragma unroll
        for (int i = 0; i < 24; i++) {
            int d = lane + i * 32;
            v[i] = 0.5f * ((x[i] - mean) * rstd * ln_g[d] + ln_b[d]) + s7[i];
        }
    }

    float pt = 0.f;
#pragma unroll
    for (int i = 0; i < 24; i++) {
        int d = lane + i * 32;
        ak[w][d] = v[i];
        pt += v[i] * target[d];
    }
    pt = warpAllSum(pt);
    if (lane == 0) tks[w] = pt;
    __syncthreads();

    if (w == 0) {
        float t0 = tks[0], t1 = tks[1], t2 = tks[2];
        float mx = fmaxf(t0, fmaxf(t1, t2));
        float e0 = __expf(t0 - mx), e1 = __expf(t1 - mx), e2 = __expf(t2 - mx);
        float inv = __fdividef(1.f, e0 + e1 + e2);
        float w0 = e0 * inv, w1 = e1 * inv, w2 = e2 * inv;

        float pj0 = 0.f, pj1 = 0.f, pj2 = 0.f;
#pragma unroll
        for (int i = 0; i < 24; i++) {
            int d = lane + i * 32;
            float f0 = w0 * ak[0][d];
            float f1 = w1 * ak[1][d];
            float f2 = w2 * ak[2][d];
            const float* w_0 = &fc2_w[d * 3];
            const float* w_1 = &fc2_w[(768 + d) * 3];
            const float* w_2 = &fc2_w[(1536 + d) * 3];
            pj0 += f0 * w_0[0] + f1 * w_1[0] + f2 * w_2[0];
            pj1 += f0 * w_0[1] + f1 * w_1[1] + f2 * w_2[1];
            pj2 += f0 * w_0[2] + f1 * w_1[2] + f2 * w_2[2];
        }
        warpAllSum3(pj0, pj1, pj2);
        if (lane == 0) {
            out[b * 3 + 0] = pj0 + fc2_b[0];
            out[b * 3 + 1] = pj1 + fc2_b[1];
            out[b * 3 + 2] = pj2 + fc2_b[2];
        }
    }
}

// ---------------- launch ----------------
extern "C" void kernel_launch(void* const* d_in, const int* in_sizes, int n_in,
                              void* d_out, int out_size) {
    (void)in_sizes; (void)n_in; (void)out_size;
    const float* bert    = (const float*)d_in[0];
    const float* target  = (const float*)d_in[1];
    const float* gc1_w   = (const float*)d_in[2];
    const float* gc1_b   = (const float*)d_in[3];
    const float* gc2_w   = (const float*)d_in[4];
    const float* gc2_b   = (const float*)d_in[5];
    const float* conv1_w = (const float*)d_in[6];
    const float* conv1_b = (const float*)d_in[7];
    const float* conv2_w = (const float*)d_in[8];
    const float* conv2_b = (const float*)d_in[9];
    const float* ln_g    = (const float*)d_in[10];
    const float* ln_b    = (const float*)d_in[11];
    const float* fc2_w   = (const float*)d_in[12];
    const float* fc2_b   = (const float*)d_in[13];
    const int*   seg     = (const int*)d_in[14];
    float* out = (float*)d_out;

    k_sent<<<544, 96>>>(bert, seg);                           // means (384) + zeroing (160)
    k_stage1<<<672, 256>>>(gc1_w, conv1_w);                   // gemm1 + conv1
    k_stage2<<<384, 256>>>(gc2_w, conv2_w, gc1_b, conv1_b);   // gemm2 + conv2
    k_final<<<64, 96>>>(target, gc2_b, conv2_b, ln_g, ln_b, fc2_w, fc2_b, out);
}

// round 11
// speedup vs baseline: 1.0376x; 1.0265x over previous
#include <cuda_runtime.h>
#include <math.h>

#define B_ 64
#define L_ 512
#define D_ 768
#define S_ 8

// ---------------- device scratch (allocation-free) ----------------
__device__ float g_sent[B_ * 4 * D_];   // rows per batch: s5,s6,s7, zero-pad
__device__ float g_acc[320 * D_];       // accA1(64) | accC1(128) | accG2(64) | accC2(64)

// packed f32x2 FMA (sm_103a: only reachable via PTX)
#define FMA2(acc, a, b) \
    asm("fma.rn.f32x2 %0, %1, %2, %0;" : "+l"(acc) : "l"(a), "l"(b))

// ---------------- K1: segment means (rows 5,6,7), 2 D-halves per row + zeroing ----------------
__global__ void __launch_bounds__(96) k_sent(const float* __restrict__ bert,
                                             const int* __restrict__ seg) {
    int bid = blockIdx.x;
    int t = threadIdx.x;
    if (bid >= 384) {
        int zt = (bid - 384) * 96 + t;
        const int stride = 160 * 96;
        for (int i = zt; i < 320 * D_; i += stride) g_acc[i] = 0.f;
        return;
    }
    int half = bid & 1;
    int r = (bid >> 1) % 3;
    int b = bid / 6;
    int s = 5 + r;
    int start = seg[b * 9 + s];
    int end   = seg[b * 9 + s + 1];
    int col = half * 96 + t;               // float4 column 0..191
    const float4* base = (const float4*)(bert + (size_t)b * L_ * D_);
    float4 a[8];
#pragma unroll
    for (int i = 0; i < 8; i++) a[i] = make_float4(0.f, 0.f, 0.f, 0.f);
    int l = start;
    for (; l + 8 <= end; l += 8) {
#pragma unroll
        for (int i = 0; i < 8; i++) {
            float4 v = base[(l + i) * 192 + col];
            a[i].x += v.x; a[i].y += v.y; a[i].z += v.z; a[i].w += v.w;
        }
    }
    for (; l < end; ++l) {
        float4 v = base[l * 192 + col];
        a[0].x += v.x; a[0].y += v.y; a[0].z += v.z; a[0].w += v.w;
    }
#pragma unroll
    for (int i = 1; i < 8; i++) {
        a[0].x += a[i].x; a[0].y += a[i].y; a[0].z += a[i].z; a[0].w += a[i].w;
    }
    float inv = 1.f / (float)(end - start);
    float4 outv = make_float4(a[0].x * inv, a[0].y * inv, a[0].z * inv, a[0].w * inv);
    ((float4*)g_sent)[b * 768 + r * 192 + col] = outv;
    if (r == 2)
        ((float4*)g_sent)[b * 768 + 3 * 192 + col] = make_float4(0.f, 0.f, 0.f, 0.f);
}

// ---------------- split-K GEMM, register-prefetch pipelined, packed f32x2 FMA ----------------
// MODE 0: A = g_sent row7                      W = gc1_w  [K,768]   C = accA1
// MODE 1: A = conv1 im2col(g_sent)             W = conv1_w [768,K]  C = accC1
// MODE 2: A = tanh(accA1+gc1_b)                W = gc2_w  [K,768]   C = accG2
// MODE 3: A = im2col(tanh(accC1+conv1_b))      W = conv2_w [768,K]  C = accC2
// kslice = 96 (NKB = 3).
template <int MODE>
__device__ __forceinline__ void gemm_body(
    const float* __restrict__ W, float* __restrict__ C,
    const float* __restrict__ bias,
    int K, int nNt, int nMt, int bid,
    float2 (*As2)[32], float (*Bs)[68])
{
    constexpr bool BT = (MODE == 1 || MODE == 3);
    const float* accA1 = g_acc;
    const float* accC1 = g_acc + 64 * 768;

    int nt = bid % nNt;
    int mt = (bid / nNt) % nMt;
    int ks = bid / (nNt * nMt);
    int k0 = ks * 96;
    const int NKB = 3;

    int tid = threadIdx.x;
    int tx = tid & 15, ty = tid >> 4;
    int n0 = nt * 64;
    int mbase = mt * 64;
    int ka = tid & 31, m0 = tid >> 5;

    float rA[8], rB[8];

    auto loadA = [&](int kb) {
        int kg = kb + ka;
        int e = 0, tap = 0;
        float bk = 0.f;
        if (MODE == 1 || MODE == 3) { e = kg / 3; tap = kg - e * 3; }
        if (MODE == 2) bk = bias[kg];
        if (MODE == 3) bk = bias[e];
#pragma unroll
        for (int j = 0; j < 8; j++) {
            int m = mbase + m0 + j * 8;
            if (MODE == 0)
                rA[j] = g_sent[m * 3072 + 1536 + kg];
            else if (MODE == 1)
                rA[j] = g_sent[(m >> 1) * 3072 + ((m & 1) + tap) * 768 + e];
            else if (MODE == 2)
                rA[j] = tanhf(accA1[m * 768 + kg] + bk);
            else
                rA[j] = (tap == 2) ? 0.f
                        : tanhf(accC1[(m * 2 + tap) * 768 + e] + bk);
        }
    };
    auto loadB = [&](int kb) {
        if (!BT) {          // W[K,768]: rows kb+ty, kb+ty+16; float4 along n
#pragma unroll
            for (int j = 0; j < 2; j++) {
                float4 v = *(const float4*)&W[(size_t)(kb + ty + j * 16) * 768 + n0 + tx * 4];
                rB[j * 4 + 0] = v.x; rB[j * 4 + 1] = v.y;
                rB[j * 4 + 2] = v.z; rB[j * 4 + 3] = v.w;
            }
        } else {            // W[768,K]: coalesced along k
#pragma unroll
            for (int j = 0; j < 8; j++)
                rB[j] = W[(size_t)(n0 + m0 + j * 8) * K + kb + ka];
        }
    };
    auto store = [&]() {
#pragma unroll
        for (int j = 0; j < 8; j++)
            As2[m0 + j * 8][ka] = make_float2(rA[j], rA[j]);
        if (!BT) {
#pragma unroll
            for (int j = 0; j < 2; j++)
                *(float4*)&Bs[ty + j * 16][tx * 4] =
                    make_float4(rB[j * 4], rB[j * 4 + 1], rB[j * 4 + 2], rB[j * 4 + 3]);
        } else {
#pragma unroll
            for (int j = 0; j < 8; j++)
                Bs[ka][m0 + j * 8] = rB[j];
        }
    };

    unsigned long long acc[4][2] = {};

    loadA(k0); loadB(k0);
    for (int i = 0; i < NKB; i++) {
        store();
        __syncthreads();
        if (i + 1 < NKB) {               // prefetch next tile: overlaps the FMA loop
            loadA(k0 + (i + 1) * 32);
            loadB(k0 + (i + 1) * 32);
        }
#pragma unroll
        for (int kk = 0; kk < 32; kk++) {
            unsigned long long a0 = *(const unsigned long long*)&As2[ty * 4 + 0][kk];
            unsigned long long a1 = *(const unsigned long long*)&As2[ty * 4 + 1][kk];
            unsigned long long a2 = *(const unsigned long long*)&As2[ty * 4 + 2][kk];
            unsigned long long a3 = *(const unsigned long long*)&As2[ty * 4 + 3][kk];
            ulonglong2 bb = *(const ulonglong2*)&Bs[kk][tx * 4];
            FMA2(acc[0][0], a0, bb.x); FMA2(acc[0][1], a0, bb.y);
            FMA2(acc[1][0], a1, bb.x); FMA2(acc[1][1], a1, bb.y);
            FMA2(acc[2][0], a2, bb.x); FMA2(acc[2][1], a2, bb.y);
            FMA2(acc[3][0], a3, bb.x); FMA2(acc[3][1], a3, bb.y);
        }
        __syncthreads();
    }
    float* Cb = C + (size_t)mbase * 768 + n0;
#pragma unroll
    for (int i = 0; i < 4; i++) {
        float2 p0 = *(float2*)&acc[i][0];
        float2 p1 = *(float2*)&acc[i][1];
        float* row = &Cb[(ty * 4 + i) * 768 + tx * 4];
        atomicAdd(&row[0], p0.x);
        atomicAdd(&row[1], p0.y);
        atomicAdd(&row[2], p1.x);
        atomicAdd(&row[3], p1.y);
    }
}

// stage 1: gemm1 (96 blocks) + conv1 (576 blocks), kslice=96
__global__ void __launch_bounds__(256, 2) k_stage1(const float* __restrict__ gc1_w,
                                                   const float* __restrict__ conv1_w) {
    __shared__ __align__(16) float2 As2[64][32];
    __shared__ __align__(16) float  Bs[32][68];
    if ((int)blockIdx.x < 96)
        gemm_body<0>(gc1_w, g_acc, nullptr, 768, 12, 1, blockIdx.x, As2, Bs);
    else
        gemm_body<1>(conv1_w, g_acc + 64 * 768, nullptr, 2304, 12, 2, blockIdx.x - 96, As2, Bs);
}

// stage 2: gemm2 (96) + conv2 (288), fused tanh-epilogue A, kslice=96
__global__ void __launch_bounds__(256, 2) k_stage2(const float* __restrict__ gc2_w,
                                                   const float* __restrict__ conv2_w,
                                                   const float* __restrict__ gc1_b,
                                                   const float* __restrict__ conv1_b) {
    __shared__ __align__(16) float2 As2[64][32];
    __shared__ __align__(16) float  Bs[32][68];
    if ((int)blockIdx.x < 96)
        gemm_body<2>(gc2_w, g_acc + 192 * 768, gc1_b, 768, 12, 1, blockIdx.x, As2, Bs);
    else
        gemm_body<3>(conv2_w, g_acc + 256 * 768, conv1_b, 2304, 12, 1, blockIdx.x - 96, As2, Bs);
}

// ---------------- warp all-reduce helpers ----------------
__device__ __forceinline__ float warpAllSum(float v) {
#pragma unroll
    for (int o = 16; o; o >>= 1) v += __shfl_xor_sync(0xffffffffu, v, o);
    return v;
}
__device__ __forceinline__ void warpAllSum2(float& a, float& b) {
#pragma unroll
    for (int o = 16; o; o >>= 1) {
        a += __shfl_xor_sync(0xffffffffu, a, o);
        b += __shfl_xor_sync(0xffffffffu, b, o);
    }
}
__device__ __forceinline__ void warpAllSum3(float& a, float& b, float& c) {
#pragma unroll
    for (int o = 16; o; o >>= 1) {
        a += __shfl_xor_sync(0xffffffffu, a, o);
        b += __shfl_xor_sync(0xffffffffu, b, o);
        c += __shfl_xor_sync(0xffffffffu, c, o);
    }
}

// ---------------- K4: hops + softmax + fc2. grid=64, block=96 (warp per branch) ----------------
__global__ void __launch_bounds__(96) k_final(
    const float* __restrict__ target, const float* __restrict__ gc2_b,
    const float* __restrict__ conv2_b, const float* __restrict__ ln_g,
    const float* __restrict__ ln_b, const float* __restrict__ fc2_w,
    const float* __restrict__ fc2_b, float* __restrict__ out)
{
    int b = blockIdx.x;
    int w = threadIdx.x >> 5;        // branch id: 0=g2, 1=conv, 2=tmask
    int lane = threadIdx.x & 31;
    const float* accG2 = g_acc + 192 * 768;
    const float* accC2 = g_acc + 256 * 768;

    __shared__ float ak[3][768];
    __shared__ float tks[3];

    float s7[24], v[24];
#pragma unroll
    for (int i = 0; i < 24; i++)
        s7[i] = g_sent[b * 3072 + 1536 + lane + i * 32];

    if (w == 2) {
        float ss = 0.f;
#pragma unroll
        for (int i = 0; i < 24; i++) ss += s7[i] * s7[i];
        ss = warpAllSum(ss);
#pragma unroll
        for (int i = 0; i < 24; i++)
            v[i] = __fdividef(1.f, 1.f + __expf(-ss * s7[i]));
    } else {
        const float* acc  = (w == 0) ? accG2 : accC2;
        const float* bias = (w == 0) ? gc2_b : conv2_b;
#pragma unroll
        for (int i = 0; i < 24; i++) {
            int d = lane + i * 32;
            v[i] = tanhf(acc[b * 768 + d] + bias[d]);
        }
    }

#pragma unroll
    for (int it = 0; it < 2; it++) {
        float pc = 0.f;
#pragma unroll
        for (int i = 0; i < 24; i++) pc += v[i] * s7[i];
        float c = warpAllSum(pc);
        float x[24], su = 0.f, sq = 0.f;
#pragma unroll
        for (int i = 0; i < 24; i++) {
            float xv = __fdividef(1.f, 1.f + __expf(-c * s7[i]));
            x[i] = xv; su += xv; sq += xv * xv;
        }
        warpAllSum2(su, sq);
        float mean = su * (1.f / 768.f);
        float m2   = sq * (1.f / 768.f);
        float rstd = rsqrtf(m2 - mean * mean + 1e-5f);
#pragma unroll
        for (int i = 0; i < 24; i++) {
            int d = lane + i * 32;
            v[i] = 0.5f * ((x[i] - mean) * rstd * ln_g[d] + ln_b[d]) + s7[i];
        }
    }

    float pt = 0.f;
#pragma unroll
    for (int i = 0; i < 24; i++) {
        int d = lane + i * 32;
        ak[w][d] = v[i];
        pt += v[i] * target[d];
    }
    pt = warpAllSum(pt);
    if (lane == 0) tks[w] = pt;
    __syncthreads();

    if (w == 0) {
        float t0 = tks[0], t1 = tks[1], t2 = tks[2];
        float mx = fmaxf(t0, fmaxf(t1, t2));
        float e0 = __expf(t0 - mx), e1 = __expf(t1 - mx), e2 = __expf(t2 - mx);
        float inv = __fdividef(1.f, e0 + e1 + e2);
        float w0 = e0 * inv, w1 = e1 * inv, w2 = e2 * inv;

        float pj0 = 0.f, pj1 = 0.f, pj2 = 0.f;
#pragma unroll
        for (int i = 0; i < 24; i++) {
            int d = lane + i * 32;
            float f0 = w0 * ak[0][d];
            float f1 = w1 * ak[1][d];
            float f2 = w2 * ak[2][d];
            const float* w_0 = &fc2_w[d * 3];
            const float* w_1 = &fc2_w[(768 + d) * 3];
            const float* w_2 = &fc2_w[(1536 + d) * 3];
            pj0 += f0 * w_0[0] + f1 * w_1[0] + f2 * w_2[0];
            pj1 += f0 * w_0[1] + f1 * w_1[1] + f2 * w_2[1];
            pj2 += f0 * w_0[2] + f1 * w_1[2] + f2 * w_2[2];
        }
        warpAllSum3(pj0, pj1, pj2);
        if (lane == 0) {
            out[b * 3 + 0] = pj0 + fc2_b[0];
            out[b * 3 + 1] = pj1 + fc2_b[1];
            out[b * 3 + 2] = pj2 + fc2_b[2];
        }
    }
}

// ---------------- launch ----------------
extern "C" void kernel_launch(void* const* d_in, const int* in_sizes, int n_in,
                              void* d_out, int out_size) {
    (void)in_sizes; (void)n_in; (void)out_size;
    const float* bert    = (const float*)d_in[0];
    const float* target  = (const float*)d_in[1];
    const float* gc1_w   = (const float*)d_in[2];
    const float* gc1_b   = (const float*)d_in[3];
    const float* gc2_w   = (const float*)d_in[4];
    const float* gc2_b   = (const float*)d_in[5];
    const float* conv1_w = (const float*)d_in[6];
    const float* conv1_b = (const float*)d_in[7];
    const float* conv2_w = (const float*)d_in[8];
    const float* conv2_b = (const float*)d_in[9];
    const float* ln_g    = (const float*)d_in[10];
    const float* ln_b    = (const float*)d_in[11];
    const float* fc2_w   = (const float*)d_in[12];
    const float* fc2_b   = (const float*)d_in[13];
    const int*   seg     = (const int*)d_in[14];
    float* out = (float*)d_out;

    k_sent<<<544, 96>>>(bert, seg);                           // means (384) + zeroing (160)
    k_stage1<<<672, 256>>>(gc1_w, conv1_w);                   // gemm1 + conv1
    k_stage2<<<384, 256>>>(gc2_w, conv2_w, gc1_b, conv1_b);   // gemm2 + conv2
    k_final<<<64, 96>>>(target, gc2_b, conv2_b, ln_g, ln_b, fc2_w, fc2_b, out);
}

// round 12
// speedup vs baseline: 1.0382x; 1.0006x over previous
#include <cuda_runtime.h>
#include <math.h>

#define B_ 64
#define L_ 512
#define D_ 768
#define S_ 8

// ---------------- device scratch (allocation-free) ----------------
__device__ float g_sent[B_ * 4 * D_];   // rows per batch: s5,s6,s7, zero-pad
__device__ float g_acc[320 * D_];       // accA1(64) | accC1(128) | accG2(64) | accC2(64)

// packed f32x2 FMA (sm_103a: only reachable via PTX)
#define FMA2(acc, a, b) \
    asm("fma.rn.f32x2 %0, %1, %2, %0;" : "+l"(acc) : "l"(a), "l"(b))

// ---------------- K1: segment means (rows 5,6,7), 2 D-halves per row + zeroing ----------------
__global__ void __launch_bounds__(96) k_sent(const float* __restrict__ bert,
                                             const int* __restrict__ seg) {
    int bid = blockIdx.x;
    int t = threadIdx.x;
    if (bid >= 384) {
        int zt = (bid - 384) * 96 + t;
        const int stride = 160 * 96;
        for (int i = zt; i < 320 * D_; i += stride) g_acc[i] = 0.f;
        return;
    }
    int half = bid & 1;
    int r = (bid >> 1) % 3;
    int b = bid / 6;
    int s = 5 + r;
    int start = seg[b * 9 + s];
    int end   = seg[b * 9 + s + 1];
    int col = half * 96 + t;               // float4 column 0..191
    const float4* base = (const float4*)(bert + (size_t)b * L_ * D_);
    float4 a[8];
#pragma unroll
    for (int i = 0; i < 8; i++) a[i] = make_float4(0.f, 0.f, 0.f, 0.f);
    int l = start;
    for (; l + 8 <= end; l += 8) {
#pragma unroll
        for (int i = 0; i < 8; i++) {
            float4 v = base[(l + i) * 192 + col];
            a[i].x += v.x; a[i].y += v.y; a[i].z += v.z; a[i].w += v.w;
        }
    }
    for (; l < end; ++l) {
        float4 v = base[l * 192 + col];
        a[0].x += v.x; a[0].y += v.y; a[0].z += v.z; a[0].w += v.w;
    }
#pragma unroll
    for (int i = 1; i < 8; i++) {
        a[0].x += a[i].x; a[0].y += a[i].y; a[0].z += a[i].z; a[0].w += a[i].w;
    }
    float inv = 1.f / (float)(end - start);
    float4 outv = make_float4(a[0].x * inv, a[0].y * inv, a[0].z * inv, a[0].w * inv);
    ((float4*)g_sent)[b * 768 + r * 192 + col] = outv;
    if (r == 2)
        ((float4*)g_sent)[b * 768 + 3 * 192 + col] = make_float4(0.f, 0.f, 0.f, 0.f);
}

// ---------------- split-K GEMM, register-prefetch pipelined, packed f32x2 FMA ----------------
// MODE 0: A = g_sent row7                      W = gc1_w  [K,768]   C = accA1
// MODE 1: A = conv1 im2col(g_sent)             W = conv1_w [768,K]  C = accC1
// MODE 2: A = tanh(accA1+gc1_b)                W = gc2_w  [K,768]   C = accG2
// MODE 3: A = im2col(tanh(accC1+conv1_b))      W = conv2_w [768,K]  C = accC2
// kslice = 96 (NKB = 3).
template <int MODE>
__device__ __forceinline__ void gemm_body(
    const float* __restrict__ W, float* __restrict__ C,
    const float* __restrict__ bias,
    int K, int nNt, int nMt, int bid,
    float2 (*As2)[32], float (*Bs)[68])
{
    constexpr bool BT = (MODE == 1 || MODE == 3);
    const float* accA1 = g_acc;
    const float* accC1 = g_acc + 64 * 768;

    int nt = bid % nNt;
    int mt = (bid / nNt) % nMt;
    int ks = bid / (nNt * nMt);
    int k0 = ks * 96;
    const int NKB = 3;

    int tid = threadIdx.x;
    int tx = tid & 15, ty = tid >> 4;
    int n0 = nt * 64;
    int mbase = mt * 64;
    int ka = tid & 31, m0 = tid >> 5;

    float rA[8], rB[8];

    auto loadA = [&](int kb) {
        int kg = kb + ka;
        int e = 0, tap = 0;
        float bk = 0.f;
        if (MODE == 1 || MODE == 3) { e = kg / 3; tap = kg - e * 3; }
        if (MODE == 2) bk = bias[kg];
        if (MODE == 3) bk = bias[e];
#pragma unroll
        for (int j = 0; j < 8; j++) {
            int m = mbase + m0 + j * 8;
            if (MODE == 0)
                rA[j] = g_sent[m * 3072 + 1536 + kg];
            else if (MODE == 1)
                rA[j] = g_sent[(m >> 1) * 3072 + ((m & 1) + tap) * 768 + e];
            else if (MODE == 2)
                rA[j] = tanhf(accA1[m * 768 + kg] + bk);
            else
                rA[j] = (tap == 2) ? 0.f
                        : tanhf(accC1[(m * 2 + tap) * 768 + e] + bk);
        }
    };
    auto loadB = [&](int kb) {
        if (!BT) {          // W[K,768]: rows kb+ty, kb+ty+16; float4 along n
#pragma unroll
            for (int j = 0; j < 2; j++) {
                float4 v = *(const float4*)&W[(size_t)(kb + ty + j * 16) * 768 + n0 + tx * 4];
                rB[j * 4 + 0] = v.x; rB[j * 4 + 1] = v.y;
                rB[j * 4 + 2] = v.z; rB[j * 4 + 3] = v.w;
            }
        } else {            // W[768,K]: coalesced along k
#pragma unroll
            for (int j = 0; j < 8; j++)
                rB[j] = W[(size_t)(n0 + m0 + j * 8) * K + kb + ka];
        }
    };
    auto store = [&]() {
#pragma unroll
        for (int j = 0; j < 8; j++)
            As2[m0 + j * 8][ka] = make_float2(rA[j], rA[j]);
        if (!BT) {
#pragma unroll
            for (int j = 0; j < 2; j++)
                *(float4*)&Bs[ty + j * 16][tx * 4] =
                    make_float4(rB[j * 4], rB[j * 4 + 1], rB[j * 4 + 2], rB[j * 4 + 3]);
        } else {
#pragma unroll
            for (int j = 0; j < 8; j++)
                Bs[ka][m0 + j * 8] = rB[j];
        }
    };

    unsigned long long acc[4][2] = {};

    loadA(k0); loadB(k0);
    for (int i = 0; i < NKB; i++) {
        store();
        __syncthreads();
        if (i + 1 < NKB) {               // prefetch next tile: overlaps the FMA loop
            loadA(k0 + (i + 1) * 32);
            loadB(k0 + (i + 1) * 32);
        }
#pragma unroll
        for (int kk = 0; kk < 32; kk++) {
            unsigned long long a0 = *(const unsigned long long*)&As2[ty * 4 + 0][kk];
            unsigned long long a1 = *(const unsigned long long*)&As2[ty * 4 + 1][kk];
            unsigned long long a2 = *(const unsigned long long*)&As2[ty * 4 + 2][kk];
            unsigned long long a3 = *(const unsigned long long*)&As2[ty * 4 + 3][kk];
            ulonglong2 bb = *(const ulonglong2*)&Bs[kk][tx * 4];
            FMA2(acc[0][0], a0, bb.x); FMA2(acc[0][1], a0, bb.y);
            FMA2(acc[1][0], a1, bb.x); FMA2(acc[1][1], a1, bb.y);
            FMA2(acc[2][0], a2, bb.x); FMA2(acc[2][1], a2, bb.y);
            FMA2(acc[3][0], a3, bb.x); FMA2(acc[3][1], a3, bb.y);
        }
        __syncthreads();
    }
    float* Cb = C + (size_t)mbase * 768 + n0;
#pragma unroll
    for (int i = 0; i < 4; i++) {
        float2 p0 = *(float2*)&acc[i][0];
        float2 p1 = *(float2*)&acc[i][1];
        float* row = &Cb[(ty * 4 + i) * 768 + tx * 4];
        atomicAdd(&row[0], p0.x);
        atomicAdd(&row[1], p0.y);
        atomicAdd(&row[2], p1.x);
        atomicAdd(&row[3], p1.y);
    }
}

// stage 1: gemm1 (96 blocks) + conv1 (576 blocks), kslice=96
__global__ void __launch_bounds__(256, 2) k_stage1(const float* __restrict__ gc1_w,
                                                   const float* __restrict__ conv1_w) {
    __shared__ __align__(16) float2 As2[64][32];
    __shared__ __align__(16) float  Bs[32][68];
    if ((int)blockIdx.x < 96)
        gemm_body<0>(gc1_w, g_acc, nullptr, 768, 12, 1, blockIdx.x, As2, Bs);
    else
        gemm_body<1>(conv1_w, g_acc + 64 * 768, nullptr, 2304, 12, 2, blockIdx.x - 96, As2, Bs);
}

// stage 2: gemm2 (96) + conv2 (288), fused tanh-epilogue A, kslice=96
__global__ void __launch_bounds__(256, 2) k_stage2(const float* __restrict__ gc2_w,
                                                   const float* __restrict__ conv2_w,
                                                   const float* __restrict__ gc1_b,
                                                   const float* __restrict__ conv1_b) {
    __shared__ __align__(16) float2 As2[64][32];
    __shared__ __align__(16) float  Bs[32][68];
    if ((int)blockIdx.x < 96)
        gemm_body<2>(gc2_w, g_acc + 192 * 768, gc1_b, 768, 12, 1, blockIdx.x, As2, Bs);
    else
        gemm_body<3>(conv2_w, g_acc + 256 * 768, conv1_b, 2304, 12, 1, blockIdx.x - 96, As2, Bs);
}

// ---------------- warp all-reduce helpers ----------------
__device__ __forceinline__ float warpAllSum(float v) {
#pragma unroll
    for (int o = 16; o; o >>= 1) v += __shfl_xor_sync(0xffffffffu, v, o);
    return v;
}
__device__ __forceinline__ void warpAllSum2(float& a, float& b) {
#pragma unroll
    for (int o = 16; o; o >>= 1) {
        a += __shfl_xor_sync(0xffffffffu, a, o);
        b += __shfl_xor_sync(0xffffffffu, b, o);
    }
}
__device__ __forceinline__ void warpAllSum3(float& a, float& b, float& c) {
#pragma unroll
    for (int o = 16; o; o >>= 1) {
        a += __shfl_xor_sync(0xffffffffu, a, o);
        b += __shfl_xor_sync(0xffffffffu, b, o);
        c += __shfl_xor_sync(0xffffffffu, c, o);
    }
}

// ---------------- K4: hops + softmax + fc2. grid=64, block=96 (warp per branch) ----------------
__global__ void __launch_bounds__(96) k_final(
    const float* __restrict__ target, const float* __restrict__ gc2_b,
    const float* __restrict__ conv2_b, const float* __restrict__ ln_g,
    const float* __restrict__ ln_b, const float* __restrict__ fc2_w,
    const float* __restrict__ fc2_b, float* __restrict__ out)
{
    int b = blockIdx.x;
    int w = threadIdx.x >> 5;        // branch id: 0=g2, 1=conv, 2=tmask
    int lane = threadIdx.x & 31;
    const float* accG2 = g_acc + 192 * 768;
    const float* accC2 = g_acc + 256 * 768;

    __shared__ float ak[3][768];
    __shared__ float tks[3];

    float s7[24], v[24];
#pragma unroll
    for (int i = 0; i < 24; i++)
        s7[i] = g_sent[b * 3072 + 1536 + lane + i * 32];

    if (w == 2) {
        float ss = 0.f;
#pragma unroll
        for (int i = 0; i < 24; i++) ss += s7[i] * s7[i];
        ss = warpAllSum(ss);
#pragma unroll
        for (int i = 0; i < 24; i++)
            v[i] = __fdividef(1.f, 1.f + __expf(-ss * s7[i]));
    } else {
        const float* acc  = (w == 0) ? accG2 : accC2;
        const float* bias = (w == 0) ? gc2_b : conv2_b;
#pragma unroll
        for (int i = 0; i < 24; i++) {
            int d = lane + i * 32;
            v[i] = tanhf(acc[b * 768 + d] + bias[d]);
        }
    }

#pragma unroll
    for (int it = 0; it < 2; it++) {
        float pc = 0.f;
#pragma unroll
        for (int i = 0; i < 24; i++) pc += v[i] * s7[i];
        float c = warpAllSum(pc);
        float x[24], su = 0.f, sq = 0.f;
#pragma unroll
        for (int i = 0; i < 24; i++) {
            float xv = __fdividef(1.f, 1.f + __expf(-c * s7[i]));
            x[i] = xv; su += xv; sq += xv * xv;
        }
        warpAllSum2(su, sq);
        float mean = su * (1.f / 768.f);
        float m2   = sq * (1.f / 768.f);
        float rstd = rsqrtf(m2 - mean * mean + 1e-5f);
#pragma unroll
        for (int i = 0; i < 24; i++) {
            int d = lane + i * 32;
            v[i] = 0.5f * ((x[i] - mean) * rstd * ln_g[d] + ln_b[d]) + s7[i];
        }
    }

    float pt = 0.f;
#pragma unroll
    for (int i = 0; i < 24; i++) {
        int d = lane + i * 32;
        ak[w][d] = v[i];
        pt += v[i] * target[d];
    }
    pt = warpAllSum(pt);
    if (lane == 0) tks[w] = pt;
    __syncthreads();

    if (w == 0) {
        float t0 = tks[0], t1 = tks[1], t2 = tks[2];
        float mx = fmaxf(t0, fmaxf(t1, t2));
        float e0 = __expf(t0 - mx), e1 = __expf(t1 - mx), e2 = __expf(t2 - mx);
        float inv = __fdividef(1.f, e0 + e1 + e2);
        float w0 = e0 * inv, w1 = e1 * inv, w2 = e2 * inv;

        float pj0 = 0.f, pj1 = 0.f, pj2 = 0.f;
#pragma unroll
        for (int i = 0; i < 24; i++) {
            int d = lane + i * 32;
            float f0 = w0 * ak[0][d];
            float f1 = w1 * ak[1][d];
            float f2 = w2 * ak[2][d];
            const float* w_0 = &fc2_w[d * 3];
            const float* w_1 = &fc2_w[(768 + d) * 3];
            const float* w_2 = &fc2_w[(1536 + d) * 3];
            pj0 += f0 * w_0[0] + f1 * w_1[0] + f2 * w_2[0];
            pj1 += f0 * w_0[1] + f1 * w_1[1] + f2 * w_2[1];
            pj2 += f0 * w_0[2] + f1 * w_1[2] + f2 * w_2[2];
        }
        warpAllSum3(pj0, pj1, pj2);
        if (lane == 0) {
            out[b * 3 + 0] = pj0 + fc2_b[0];
            out[b * 3 + 1] = pj1 + fc2_b[1];
            out[b * 3 + 2] = pj2 + fc2_b[2];
        }
    }
}

// ---------------- launch ----------------
extern "C" void kernel_launch(void* const* d_in, const int* in_sizes, int n_in,
                              void* d_out, int out_size) {
    (void)in_sizes; (void)n_in; (void)out_size;
    const float* bert    = (const float*)d_in[0];
    const float* target  = (const float*)d_in[1];
    const float* gc1_w   = (const float*)d_in[2];
    const float* gc1_b   = (const float*)d_in[3];
    const float* gc2_w   = (const float*)d_in[4];
    const float* gc2_b   = (const float*)d_in[5];
    const float* conv1_w = (const float*)d_in[6];
    const float* conv1_b = (const float*)d_in[7];
    const float* conv2_w = (const float*)d_in[8];
    const float* conv2_b = (const float*)d_in[9];
    const float* ln_g    = (const float*)d_in[10];
    const float* ln_b    = (const float*)d_in[11];
    const float* fc2_w   = (const float*)d_in[12];
    const float* fc2_b   = (const float*)d_in[13];
    const int*   seg     = (const int*)d_in[14];
    float* out = (float*)d_out;

    k_sent<<<544, 96>>>(bert, seg);                           // means (384) + zeroing (160)
    k_stage1<<<672, 256>>>(gc1_w, conv1_w);                   // gemm1 + conv1
    k_stage2<<<384, 256>>>(gc2_w, conv2_w, gc1_b, conv1_b);   // gemm2 + conv2
    k_final<<<64, 96>>>(target, gc2_b, conv2_b, ln_g, ln_b, fc2_w, fc2_b, out);
}